// round 10
// baseline (speedup 1.0000x reference)
#include <cuda_runtime.h>
#include <cuda_bf16.h>
#include <math_constants.h>
#include <cstdint>

// Problem constants
#define Bq  2
#define Lq  2048
#define Dq  1024
#define Hq  16
#define HDq 64
#define Uq  8
#define SCALE 0.03125f   // 1/sqrt(1024), exact power of two
#define GAP_THRESH 2e-4f

#define NKT 32
#define NTILES (Lq / NKT)   // 64

typedef unsigned long long u64;
typedef unsigned int u32;

// ---------------- packed f32x2 helpers ----------------
__device__ __forceinline__ u64 ffma2(u64 a, u64 b, u64 c) {
    u64 d; asm("fma.rn.f32x2 %0, %1, %2, %3;" : "=l"(d) : "l"(a), "l"(b), "l"(c));
    return d;
}
__device__ __forceinline__ u64 fadd2(u64 a, u64 b) {
    u64 d; asm("add.rn.f32x2 %0, %1, %2;" : "=l"(d) : "l"(a), "l"(b));
    return d;
}
__device__ __forceinline__ u64 pack2(float x, float y) {
    u64 r; asm("mov.b64 %0, {%1, %2};" : "=l"(r) : "f"(x), "f"(y));
    return r;
}
__device__ __forceinline__ void unpack2(u64 v, float& x, float& y) {
    asm("mov.b64 {%0, %1}, %2;" : "=f"(x), "=f"(y) : "l"(v));
}

// ---------------- warp MMA helpers ----------------
__device__ __forceinline__ u32 smem_u32(const void* p) {
    u32 a;
    asm("{ .reg .u64 t; cvta.to.shared.u64 t, %1; cvt.u32.u64 %0, t; }"
        : "=r"(a) : "l"(p));
    return a;
}
__device__ __forceinline__ void ldsm_x4(u32 addr, u32& r0, u32& r1, u32& r2, u32& r3) {
    asm volatile("ldmatrix.sync.aligned.m8n8.x4.shared.b16 {%0,%1,%2,%3}, [%4];"
                 : "=r"(r0), "=r"(r1), "=r"(r2), "=r"(r3) : "r"(addr));
}
__device__ __forceinline__ void ldsm_x2(u32 addr, u32& r0, u32& r1) {
    asm volatile("ldmatrix.sync.aligned.m8n8.x2.shared.b16 {%0,%1}, [%2];"
                 : "=r"(r0), "=r"(r1) : "r"(addr));
}
__device__ __forceinline__ void mma_bf16(float& c0, float& c1, float& c2, float& c3,
                                         u32 a0, u32 a1, u32 a2, u32 a3,
                                         u32 b0, u32 b1) {
    asm volatile(
        "mma.sync.aligned.m16n8k16.row.col.f32.bf16.bf16.f32 "
        "{%0,%1,%2,%3}, {%4,%5,%6,%7}, {%8,%9}, {%0,%1,%2,%3};"
        : "+f"(c0), "+f"(c1), "+f"(c2), "+f"(c3)
        : "r"(a0), "r"(a1), "r"(a2), "r"(a3), "r"(b0), "r"(b1));
}
__device__ __forceinline__ u32 cvt2bf(float hi, float lo) {
    u32 r; asm("cvt.rn.bf16x2.f32 %0, %1, %2;" : "=r"(r) : "f"(hi), "f"(lo));
    return r;
}

// top-N streaming insert: strict > enters (ascending scan keeps lowest index);
// evict min value, tie -> largest index. Matches jax.lax.top_k.
template<int N>
__device__ __forceinline__ void topN_insert(float (&tv)[N], int (&ti)[N],
                                            float& runmin, float s, int kidx) {
    if (s > runmin) {
        int m = 0; float mv = tv[0]; int mi = ti[0];
#pragma unroll
        for (int j = 1; j < N; j++) {
            bool take = (tv[j] < mv) || (tv[j] == mv && ti[j] > mi);
            if (take) { m = j; mv = tv[j]; mi = ti[j]; }
        }
#pragma unroll
        for (int j = 0; j < N; j++)
            if (j == m) { tv[j] = s; ti[j] = kidx; }
        float nm = tv[0];
#pragma unroll
        for (int j = 1; j < N; j++) nm = fminf(nm, tv[j]);
        runmin = nm;
    }
}

// Scratch context buffer
__device__ __align__(16) float g_ctx[(size_t)Bq * Lq * Dq];

// Dynamic smem (49152 B, zero static smem):
//  phase Q : planes at 0 / 16384 / 32768 (128 rows x 128B, swizzled)
//  main    : K planes at 0 / 4096 / 8192 (32 rows x 128B each);
//            scores f32 [128][33] at 12288 (16896B -> ends 29184)
//  post    : sW [128][8] at 0, sI [128][8] at 4096, rescue scores at 8192
//            (2048 f32 -> 16384), qvec at 16384, s_list at 20480, s_cnt 20992
#define KP1_OFF  4096
#define KP2_OFF  8192
#define SC_OFF   12288
#define SW_OFF   0
#define SI_OFF   4096
#define RS_OFF   8192
#define RQ_OFF   16384
#define SL_OFF   20480
#define CN_OFF   20992

// ---------------------------------------------------------------------------
__global__ __launch_bounds__(128) void attn_topk_kernel(
    const float* __restrict__ Q,
    const float* __restrict__ K,
    const float* __restrict__ V,
    float* __restrict__ attnw,
    int write_w)
{
    extern __shared__ __align__(16) char dsm[];
    const u32 sbase = smem_u32(dsm);
    int* s_list = (int*)(dsm + SL_OFF);
    int* s_cnt  = (int*)(dsm + CN_OFF);

    const int tid = threadIdx.x;
    const int lane = tid & 31;
    const int wrp = tid >> 5;
    const int b = blockIdx.z;
    const int h = blockIdx.y;
    const int qbase = blockIdx.x * 128;

    // ===== Phase 1: Q -> 3 bf16 planes in smem (swizzled, 128B rows) =====
    {
        const float4* qp = (const float4*)(Q + ((size_t)(b * Lq + qbase + tid)) * Dq + h * HDq);
        float r[64];
#pragma unroll
        for (int i = 0; i < 16; i++) {
            float4 t = qp[i];
            r[4 * i] = t.x; r[4 * i + 1] = t.y; r[4 * i + 2] = t.z; r[4 * i + 3] = t.w;
        }
#pragma unroll
        for (int p = 0; p < 3; p++) {
            u32 pk[32];
#pragma unroll
            for (int j = 0; j < 32; j++) {
                u32 c = cvt2bf(r[2 * j + 1], r[2 * j]);
                pk[j] = c;
                if (p < 2) {
                    r[2 * j]     -= __uint_as_float(c << 16);
                    r[2 * j + 1] -= __uint_as_float(c & 0xFFFF0000u);
                }
            }
#pragma unroll
            for (int i = 0; i < 8; i++) {
                u32 off = p * 16384 + tid * 128 + ((u32)(i ^ (tid & 7))) * 16;
                *(uint4*)(dsm + off) = *(uint4*)&pk[4 * i];
            }
        }
    }
    __syncthreads();

    // ===== Phase 2: A fragments -> registers (warp owns 32 queries) =====
    u32 A[3][2][4][4];
    {
        const int t4 = lane >> 3;
        const int r8 = lane & 7;
#pragma unroll
        for (int p = 0; p < 3; p++)
#pragma unroll
            for (int mt = 0; mt < 2; mt++)
#pragma unroll
                for (int ks = 0; ks < 4; ks++) {
                    u32 row = (u32)(wrp * 32 + mt * 16 + (t4 & 1) * 8 + r8);
                    u32 ch = (u32)(ks * 2 + (t4 >> 1));
                    u32 addr = sbase + p * 16384 + row * 128 + ((ch ^ (row & 7)) * 16);
                    ldsm_x4(addr, A[p][mt][ks][0], A[p][mt][ks][1],
                                  A[p][mt][ks][2], A[p][mt][ks][3]);
                }
    }
    __syncthreads();   // Q planes dead; K planes may overwrite

    // top-9 state per thread (query qbase + tid)
    float tv[9]; int ti[9]; float rmn = -CUDART_INF_F;
#pragma unroll
    for (int j = 0; j < 9; j++) { tv[j] = -CUDART_INF_F; ti[j] = 0; }

    float4* wz = (float4*)(attnw + ((size_t)((b * Hq + h) * Lq + qbase)) * Lq);

    // K staging: thread covers key tid>>2 (32 keys), dims (tid&3)*16 .. +15
    const int krow = tid >> 2;
    const int kd0 = (tid & 3) * 16;
    const int QP[6] = {0, 1, 2, 0, 1, 0};
    const int KP[6] = {0, 0, 0, 1, 1, 2};
    const int ll = lane & 15;

    for (int t = 0; t < NTILES; t++) {
        // ---- load K tile fp32 (32 keys x 64 dims), split to 3 planes ----
        {
            const float4* kp = (const float4*)(K +
                ((size_t)(b * Lq + t * NKT + krow)) * Dq + h * HDq + kd0);
            float e[16];
#pragma unroll
            for (int i = 0; i < 4; i++) {
                float4 v = kp[i];
                e[4 * i] = v.x; e[4 * i + 1] = v.y; e[4 * i + 2] = v.z; e[4 * i + 3] = v.w;
            }
            u32 p0[8], p1[8], p2[8];
#pragma unroll
            for (int j = 0; j < 8; j++) {
                float a = e[2 * j], c = e[2 * j + 1];
                u32 v0 = cvt2bf(c, a);
                a -= __uint_as_float(v0 << 16);
                c -= __uint_as_float(v0 & 0xFFFF0000u);
                u32 v1 = cvt2bf(c, a);
                a -= __uint_as_float(v1 << 16);
                c -= __uint_as_float(v1 & 0xFFFF0000u);
                u32 v2 = cvt2bf(c, a);
                p0[j] = v0; p1[j] = v1; p2[j] = v2;
            }
#pragma unroll
            for (int i = 0; i < 2; i++) {
                u32 ch = (u32)((tid & 3) * 2 + i);
                u32 off = (u32)krow * 128 + ((ch ^ ((u32)krow & 7)) * 16);
                *(uint4*)(dsm + off)           = *(uint4*)&p0[4 * i];
                *(uint4*)(dsm + KP1_OFF + off) = *(uint4*)&p1[4 * i];
                *(uint4*)(dsm + KP2_OFF + off) = *(uint4*)&p2[4 * i];
            }
        }
        // zero-fill this tile's slice of attnw (128 rows x 32 floats)
        if (write_w) {
            const float4 z = make_float4(0.f, 0.f, 0.f, 0.f);
            float4* zp = wz + (size_t)t * 1024;
#pragma unroll
            for (int i = 0; i < 8; i++) zp[i * 128 + tid] = z;
        }
        __syncthreads();   // K planes ready

        // ---- MMA: 4 n-tiles of 8 keys; scores -> smem [128][33] ----
#pragma unroll
        for (int nt = 0; nt < 4; nt++) {
            u32 Bf[3][4][2];
            {
                u32 row = (u32)(nt * 8 + (ll & 7));
                u32 swr = (row & 7);
#pragma unroll
                for (int ks = 0; ks < 4; ks++) {
                    u32 ch = (u32)(ks * 2 + (ll >> 3));
                    u32 off = row * 128 + ((ch ^ swr) * 16);
                    ldsm_x2(sbase + off,           Bf[0][ks][0], Bf[0][ks][1]);
                    ldsm_x2(sbase + KP1_OFF + off, Bf[1][ks][0], Bf[1][ks][1]);
                    ldsm_x2(sbase + KP2_OFF + off, Bf[2][ks][0], Bf[2][ks][1]);
                }
            }
            float cA0 = 0.f, cA1 = 0.f, cA2 = 0.f, cA3 = 0.f;
            float cB0 = 0.f, cB1 = 0.f, cB2 = 0.f, cB3 = 0.f;
#pragma unroll
            for (int pp = 0; pp < 6; pp++) {
                const int qp = QP[pp], kp = KP[pp];
#pragma unroll
                for (int ks = 0; ks < 4; ks++) {
                    mma_bf16(cA0, cA1, cA2, cA3,
                             A[qp][0][ks][0], A[qp][0][ks][1],
                             A[qp][0][ks][2], A[qp][0][ks][3],
                             Bf[kp][ks][0], Bf[kp][ks][1]);
                    mma_bf16(cB0, cB1, cB2, cB3,
                             A[qp][1][ks][0], A[qp][1][ks][1],
                             A[qp][1][ks][2], A[qp][1][ks][3],
                             Bf[kp][ks][0], Bf[kp][ks][1]);
                }
            }
            // scatter C frags: row q, col = key within tile (0..31)
            {
                const int q0 = wrp * 32 + (lane >> 2);
                const int kk = nt * 8 + (lane & 3) * 2;
                float* sc = (float*)(dsm + SC_OFF);
                sc[(q0 +  0) * 33 + kk]     = cA0;
                sc[(q0 +  0) * 33 + kk + 1] = cA1;
                sc[(q0 +  8) * 33 + kk]     = cA2;
                sc[(q0 +  8) * 33 + kk + 1] = cA3;
                sc[(q0 + 16) * 33 + kk]     = cB0;
                sc[(q0 + 16) * 33 + kk + 1] = cB1;
                sc[(q0 + 24) * 33 + kk]     = cB2;
                sc[(q0 + 24) * 33 + kk + 1] = cB3;
            }
        }
        __syncthreads();   // scores ready; K-plane reads done

        // ---- stream this thread's 32 scores (ascending keys), top-9 ----
        {
            const float* srow = (const float*)(dsm + SC_OFF) + tid * 33;
#pragma unroll 8
            for (int k = 0; k < NKT; k++) {
                float s = srow[k];
                topN_insert<9>(tv, ti, rmn, s, t * NKT + k);
            }
        }
        __syncthreads();   // scan done before next tile overwrites
    }

    // ===== init flag state =====
    if (tid == 0) *s_cnt = 0;
    __syncthreads();

    // ===== identify worst (9th); flag near-ties (8th-vs-9th gap) =====
    int w1 = 0;
    {
        float v1 = tv[0]; int i1 = ti[0];
#pragma unroll
        for (int j = 1; j < 9; j++) {
            bool worse = (tv[j] < v1) || (tv[j] == v1 && ti[j] > i1);
            if (worse) { w1 = j; v1 = tv[j]; i1 = ti[j]; }
        }
        float v2 = CUDART_INF_F;
#pragma unroll
        for (int j = 0; j < 9; j++)
            if (j != w1) v2 = fminf(v2, tv[j]);
        if (v2 - v1 < GAP_THRESH) {
            int idx = atomicAdd(s_cnt, 1);
            if (idx < 128) s_list[idx] = tid;
        }
    }

    // ===== softmax over the kept 8; write to sW/sI =====
    __syncthreads();
    {
        float kv[8]; int ki[8]; int c = 0;
#pragma unroll
        for (int j = 0; j < 9; j++)
            if (j != w1) { kv[c] = tv[j]; ki[c] = ti[j]; c++; }
        float mx = kv[0];
#pragma unroll
        for (int j = 1; j < 8; j++) mx = fmaxf(mx, kv[j]);
        float w[8]; float wsum = 0.f;
#pragma unroll
        for (int j = 0; j < 8; j++) { w[j] = expf((kv[j] - mx) * SCALE); wsum += w[j]; }
        float inv = 1.f / wsum;
        float* sW = (float*)(dsm + SW_OFF);
        int*   sI = (int*)(dsm + SI_OFF);
#pragma unroll
        for (int j = 0; j < 8; j++) { sW[tid * 8 + j] = w[j] * inv; sI[tid * 8 + j] = ki[j]; }
    }
    __syncthreads();

    // ===== rescue: recompute flagged rows with exact fp32 f32x2 chain =====
    {
        int ncnt = *s_cnt; if (ncnt > 128) ncnt = 128;
        float* sresc = (float*)(dsm + RS_OFF);
        float* qvec  = (float*)(dsm + RQ_OFF);
        for (int r = 0; r < ncnt; r++) {
            int qq = s_list[r];
            if (tid < 16)
                ((float4*)qvec)[tid] =
                    ((const float4*)(Q + ((size_t)(b * Lq + qbase + qq)) * Dq + h * HDq))[tid];
            __syncthreads();
            u64 q2[32];
            {
                const ulonglong2* qp2 = (const ulonglong2*)qvec;
#pragma unroll
                for (int i = 0; i < 16; i++) {
                    ulonglong2 v = qp2[i];
                    q2[2 * i] = v.x; q2[2 * i + 1] = v.y;
                }
            }
            for (int i = 0; i < 16; i++) {
                int kidx = tid + 128 * i;
                const ulonglong2* kp =
                    (const ulonglong2*)(K + ((size_t)(b * Lq + kidx)) * Dq + h * HDq);
                u64 a0 = 0ull, a1 = 0ull, a2 = 0ull, a3 = 0ull;
#pragma unroll
                for (int ii = 0; ii < 16; ii += 2) {
                    ulonglong2 k0 = kp[ii];
                    ulonglong2 k1 = kp[ii + 1];
                    a0 = ffma2(q2[2 * ii + 0], k0.x, a0);
                    a1 = ffma2(q2[2 * ii + 1], k0.y, a1);
                    a2 = ffma2(q2[2 * ii + 2], k1.x, a2);
                    a3 = ffma2(q2[2 * ii + 3], k1.y, a3);
                }
                u64 a = fadd2(fadd2(a0, a1), fadd2(a2, a3));
                float slo, shi; unpack2(a, slo, shi);
                sresc[kidx] = slo + shi;
            }
            __syncthreads();
            if (tid == 0) {
                float tv8[8]; int ti8[8]; float rm = -CUDART_INF_F;
#pragma unroll
                for (int j = 0; j < 8; j++) { tv8[j] = -CUDART_INF_F; ti8[j] = 0; }
                for (int k = 0; k < Lq; k++)
                    topN_insert<8>(tv8, ti8, rm, sresc[k], k);
                float mx = tv8[0];
#pragma unroll
                for (int j = 1; j < 8; j++) mx = fmaxf(mx, tv8[j]);
                float w8[8]; float wsum = 0.f;
#pragma unroll
                for (int j = 0; j < 8; j++) { w8[j] = expf((tv8[j] - mx) * SCALE); wsum += w8[j]; }
                float inv = 1.f / wsum;
                float* sW = (float*)(dsm + SW_OFF);
                int*   sI = (int*)(dsm + SI_OFF);
#pragma unroll
                for (int j = 0; j < 8; j++) { sW[qq * 8 + j] = w8[j] * inv; sI[qq * 8 + j] = ti8[j]; }
            }
            __syncthreads();
        }
    }

    // ===== scatter attn_weights =====
    if (write_w) {
        const float* sW = (const float*)(dsm + SW_OFF);
        const int*   sI = (const int*)(dsm + SI_OFF);
        float* wrow = attnw + ((size_t)((b * Hq + h) * Lq + qbase + tid)) * Lq;
#pragma unroll
        for (int j = 0; j < 8; j++) wrow[sI[tid * 8 + j]] = sW[tid * 8 + j];
    }

    // ===== coalesced V gather =====
    {
        const float* sW = (const float*)(dsm + SW_OFF);
        const int*   sI = (const int*)(dsm + SI_OFF);
        for (int qq = wrp * 32; qq < wrp * 32 + 32; qq++) {
            float2 acc = make_float2(0.f, 0.f);
#pragma unroll
            for (int j = 0; j < 8; j++) {
                float wv = sW[qq * 8 + j];
                int kidx = sI[qq * 8 + j];
                const float2* vp =
                    (const float2*)(V + ((size_t)(b * Lq + kidx)) * Dq + h * HDq);
                float2 vv = vp[lane];
                acc.x = fmaf(wv, vv.x, acc.x);
                acc.y = fmaf(wv, vv.y, acc.y);
            }
            float2* cp = (float2*)(g_ctx + ((size_t)(b * Lq + qbase + qq)) * Dq + h * HDq);
            cp[lane] = acc;
        }
    }
}

// ---------------------------------------------------------------------------
// Kernel 2: output projection (unchanged): 128x128 tile, BK=8, 8x8 f32x2.
// ---------------------------------------------------------------------------
#define PM 128
#define PN 128
#define PK 8
#define PPAD 132

__global__ __launch_bounds__(256) void proj_kernel(
    const float* __restrict__ Wt,
    const float* __restrict__ bias,
    float* __restrict__ Cout)
{
    __shared__ __align__(16) float As[PK][PPAD];
    __shared__ __align__(16) float Bs[PK][PPAD];

    const int tid = threadIdx.x;
    const int tx = tid & 15;
    const int ty = tid >> 4;
    const int m0 = blockIdx.y * PM;
    const int n0 = blockIdx.x * PN;
    const int lr = tid >> 1;
    const int lk = (tid & 1) * 4;

    u64 acc[8][4];
#pragma unroll
    for (int i = 0; i < 8; i++)
#pragma unroll
        for (int p = 0; p < 4; p++) acc[i][p] = 0ull;

    const float* aptr = g_ctx + (size_t)(m0 + lr) * Dq + lk;
    const float* bptr = Wt + (size_t)(n0 + lr) * Dq + lk;
    float4 av = *(const float4*)aptr;
    float4 bv = *(const float4*)bptr;

    for (int k0 = 0; k0 < Dq; k0 += PK) {
        __syncthreads();
        As[lk + 0][lr] = av.x; As[lk + 1][lr] = av.y;
        As[lk + 2][lr] = av.z; As[lk + 3][lr] = av.w;
        Bs[lk + 0][lr] = bv.x; Bs[lk + 1][lr] = bv.y;
        Bs[lk + 2][lr] = bv.z; Bs[lk + 3][lr] = bv.w;
        if (k0 + PK < Dq) {
            av = *(const float4*)(aptr + k0 + PK);
            bv = *(const float4*)(bptr + k0 + PK);
        }
        __syncthreads();

#pragma unroll
        for (int k = 0; k < PK; k++) {
            float4 a0 = *(const float4*)&As[k][ty * 8];
            float4 a1 = *(const float4*)&As[k][ty * 8 + 4];
            ulonglong2 b0 = *(const ulonglong2*)&Bs[k][tx * 8];
            ulonglong2 b1 = *(const ulonglong2*)&Bs[k][tx * 8 + 4];
            u64 aa;
            aa = pack2(a0.x, a0.x);
            acc[0][0] = ffma2(aa, b0.x, acc[0][0]);
            acc[0][1] = ffma2(aa, b0.y, acc[0][1]);
            acc[0][2] = ffma2(aa, b1.x, acc[0][2]);
            acc[0][3] = ffma2(aa, b1.y, acc[0][3]);
            aa = pack2(a0.y, a0.y);
            acc[1][0] = ffma2(aa, b0.x, acc[1][0]);
            acc[1][1] = ffma2(aa, b0.y, acc[1][1]);
            acc[1][2] = ffma2(aa, b1.x, acc[1][2]);
            acc[1][3] = ffma2(aa, b1.y, acc[1][3]);
            aa = pack2(a0.z, a0.z);
            acc[2][0] = ffma2(aa, b0.x, acc[2][0]);
            acc[2][1] = ffma2(aa, b0.y, acc[2][1]);
            acc[2][2] = ffma2(aa, b1.x, acc[2][2]);
            acc[2][3] = ffma2(aa, b1.y, acc[2][3]);
            aa = pack2(a0.w, a0.w);
            acc[3][0] = ffma2(aa, b0.x, acc[3][0]);
            acc[3][1] = ffma2(aa, b0.y, acc[3][1]);
            acc[3][2] = ffma2(aa, b1.x, acc[3][2]);
            acc[3][3] = ffma2(aa, b1.y, acc[3][3]);
            aa = pack2(a1.x, a1.x);
            acc[4][0] = ffma2(aa, b0.x, acc[4][0]);
            acc[4][1] = ffma2(aa, b0.y, acc[4][1]);
            acc[4][2] = ffma2(aa, b1.x, acc[4][2]);
            acc[4][3] = ffma2(aa, b1.y, acc[4][3]);
            aa = pack2(a1.y, a1.y);
            acc[5][0] = ffma2(aa, b0.x, acc[5][0]);
            acc[5][1] = ffma2(aa, b0.y, acc[5][1]);
            acc[5][2] = ffma2(aa, b1.x, acc[5][2]);
            acc[5][3] = ffma2(aa, b1.y, acc[5][3]);
            aa = pack2(a1.z, a1.z);
            acc[6][0] = ffma2(aa, b0.x, acc[6][0]);
            acc[6][1] = ffma2(aa, b0.y, acc[6][1]);
            acc[6][2] = ffma2(aa, b1.x, acc[6][2]);
            acc[6][3] = ffma2(aa, b1.y, acc[6][3]);
            aa = pack2(a1.w, a1.w);
            acc[7][0] = ffma2(aa, b0.x, acc[7][0]);
            acc[7][1] = ffma2(aa, b0.y, acc[7][1]);
            acc[7][2] = ffma2(aa, b1.x, acc[7][2]);
            acc[7][3] = ffma2(aa, b1.y, acc[7][3]);
        }
    }

    ulonglong2 bb0 = *(const ulonglong2*)&bias[n0 + tx * 8];
    ulonglong2 bb1 = *(const ulonglong2*)&bias[n0 + tx * 8 + 4];
#pragma unroll
    for (int i = 0; i < 8; i++) {
        u64 c0 = fadd2(acc[i][0], bb0.x);
        u64 c1 = fadd2(acc[i][1], bb0.y);
        u64 c2 = fadd2(acc[i][2], bb1.x);
        u64 c3 = fadd2(acc[i][3], bb1.y);
        float* crow = Cout + (size_t)(m0 + ty * 8 + i) * Dq + n0 + tx * 8;
        ((ulonglong2*)crow)[0] = make_ulonglong2(c0, c1);
        ((ulonglong2*)crow)[1] = make_ulonglong2(c2, c3);
    }
}

// ---------------------------------------------------------------------------
extern "C" void kernel_launch(void* const* d_in, const int* in_sizes, int n_in,
                              void* d_out, int out_size)
{
    const float* Q    = (const float*)d_in[0];
    const float* K    = (const float*)d_in[1];
    const float* V    = (const float*)d_in[2];
    const float* W    = (const float*)d_in[3];
    const float* bias = (const float*)d_in[4];
    float* out = (float*)d_out;

    const size_t N_ATT = (size_t)Bq * Lq * Dq;
    const size_t N_W   = (size_t)Bq * Hq * Lq * Lq;
    const int has_w = ((size_t)out_size >= N_ATT + N_W) ? 1 : 0;
    float* attnw = out + N_ATT;

    dim3 g1(Lq / 128, Hq, Bq);
    attn_topk_kernel<<<g1, 128, 49152>>>(Q, K, V, attnw, has_w);

    dim3 g2(Dq / PN, (Bq * Lq) / PM);
    proj_kernel<<<g2, 256>>>(W, bias, out);
}

// round 12
// speedup vs baseline: 1.3310x; 1.3310x over previous
#include <cuda_runtime.h>
#include <cuda_bf16.h>
#include <math_constants.h>
#include <cstdint>

// Problem constants
#define Bq  2
#define Lq  2048
#define Dq  1024
#define Hq  16
#define HDq 64
#define Uq  8
#define SCALE 0.03125f   // 1/sqrt(1024), exact power of two
#define GAP_THRESH 4e-4f

#define NKT 32
#define NTILES (Lq / NKT)   // 64

typedef unsigned long long u64;
typedef unsigned int u32;

// ---------------- packed f32x2 helpers ----------------
__device__ __forceinline__ u64 ffma2(u64 a, u64 b, u64 c) {
    u64 d; asm("fma.rn.f32x2 %0, %1, %2, %3;" : "=l"(d) : "l"(a), "l"(b), "l"(c));
    return d;
}
__device__ __forceinline__ u64 fadd2(u64 a, u64 b) {
    u64 d; asm("add.rn.f32x2 %0, %1, %2;" : "=l"(d) : "l"(a), "l"(b));
    return d;
}
__device__ __forceinline__ u64 pack2(float x, float y) {
    u64 r; asm("mov.b64 %0, {%1, %2};" : "=l"(r) : "f"(x), "f"(y));
    return r;
}
__device__ __forceinline__ void unpack2(u64 v, float& x, float& y) {
    asm("mov.b64 {%0, %1}, %2;" : "=f"(x), "=f"(y) : "l"(v));
}

// ---------------- warp MMA helpers ----------------
__device__ __forceinline__ u32 smem_u32(const void* p) {
    u32 a;
    asm("{ .reg .u64 t; cvta.to.shared.u64 t, %1; cvt.u32.u64 %0, t; }"
        : "=r"(a) : "l"(p));
    return a;
}
__device__ __forceinline__ void ldsm_x4(u32 addr, u32& r0, u32& r1, u32& r2, u32& r3) {
    asm volatile("ldmatrix.sync.aligned.m8n8.x4.shared.b16 {%0,%1,%2,%3}, [%4];"
                 : "=r"(r0), "=r"(r1), "=r"(r2), "=r"(r3) : "r"(addr));
}
__device__ __forceinline__ void ldsm_x2(u32 addr, u32& r0, u32& r1) {
    asm volatile("ldmatrix.sync.aligned.m8n8.x2.shared.b16 {%0,%1}, [%2];"
                 : "=r"(r0), "=r"(r1) : "r"(addr));
}
__device__ __forceinline__ void mma_bf16(float& c0, float& c1, float& c2, float& c3,
                                         u32 a0, u32 a1, u32 a2, u32 a3,
                                         u32 b0, u32 b1) {
    asm volatile(
        "mma.sync.aligned.m16n8k16.row.col.f32.bf16.bf16.f32 "
        "{%0,%1,%2,%3}, {%4,%5,%6,%7}, {%8,%9}, {%0,%1,%2,%3};"
        : "+f"(c0), "+f"(c1), "+f"(c2), "+f"(c3)
        : "r"(a0), "r"(a1), "r"(a2), "r"(a3), "r"(b0), "r"(b1));
}
__device__ __forceinline__ u32 cvt2bf(float hi, float lo) {
    u32 r; asm("cvt.rn.bf16x2.f32 %0, %1, %2;" : "=r"(r) : "f"(hi), "f"(lo));
    return r;
}

// top-N streaming insert: strict > enters (ascending scan keeps lowest index);
// evict min value, tie -> largest index. Matches jax.lax.top_k.
template<int N>
__device__ __forceinline__ void topN_insert(float (&tv)[N], int (&ti)[N],
                                            float& runmin, float s, int kidx) {
    if (s > runmin) {
        int m = 0; float mv = tv[0]; int mi = ti[0];
#pragma unroll
        for (int j = 1; j < N; j++) {
            bool take = (tv[j] < mv) || (tv[j] == mv && ti[j] > mi);
            if (take) { m = j; mv = tv[j]; mi = ti[j]; }
        }
#pragma unroll
        for (int j = 0; j < N; j++)
            if (j == m) { tv[j] = s; ti[j] = kidx; }
        float nm = tv[0];
#pragma unroll
        for (int j = 1; j < N; j++) nm = fminf(nm, tv[j]);
        runmin = nm;
    }
}

// Scratch context buffer
__device__ __align__(16) float g_ctx[(size_t)Bq * Lq * Dq];

// Dynamic smem (32768 B, zero static) — R9-validated layout, plane 2 unused:
//  phase Q : 2 planes at 0 / 16384 (128 rows x 128B, swizzled; plane1 ends 32768)
//  main    : K planes at 0 / 4096 (32 rows x 128B each);
//            scores f32 [128][33] at 12288 (16896B -> ends 29184)
//  post    : sW [128][8] at 0, sI at 4096, rescue scores at 8192 (2048 f32
//            -> 16384), qvec at 16384, s_list at 20480, s_cnt 20992
#define KP1_OFF  4096
#define SC_OFF   12288
#define SW_OFF   0
#define SI_OFF   4096
#define RS_OFF   8192
#define RQ_OFF   16384
#define SL_OFF   20480
#define CN_OFF   20992
#define DSM_SZ   32768

// ---------------------------------------------------------------------------
__global__ __launch_bounds__(128) void attn_topk_kernel(
    const float* __restrict__ Q,
    const float* __restrict__ K,
    const float* __restrict__ V,
    float* __restrict__ attnw,
    int write_w)
{
    extern __shared__ __align__(16) char dsm[];
    const u32 sbase = smem_u32(dsm);
    int* s_list = (int*)(dsm + SL_OFF);
    int* s_cnt  = (int*)(dsm + CN_OFF);

    const int tid = threadIdx.x;
    const int lane = tid & 31;
    const int wrp = tid >> 5;
    const int b = blockIdx.z;
    const int h = blockIdx.y;
    const int qbase = blockIdx.x * 128;

    // ===== Phase 1: Q -> 2 bf16 planes in smem (swizzled, 128B rows) =====
    {
        const float4* qp = (const float4*)(Q + ((size_t)(b * Lq + qbase + tid)) * Dq + h * HDq);
        float r[64];
#pragma unroll
        for (int i = 0; i < 16; i++) {
            float4 t = qp[i];
            r[4 * i] = t.x; r[4 * i + 1] = t.y; r[4 * i + 2] = t.z; r[4 * i + 3] = t.w;
        }
#pragma unroll
        for (int p = 0; p < 2; p++) {
            u32 pk[32];
#pragma unroll
            for (int j = 0; j < 32; j++) {
                u32 c = cvt2bf(r[2 * j + 1], r[2 * j]);
                pk[j] = c;
                if (p < 1) {
                    r[2 * j]     -= __uint_as_float(c << 16);
                    r[2 * j + 1] -= __uint_as_float(c & 0xFFFF0000u);
                }
            }
#pragma unroll
            for (int i = 0; i < 8; i++) {
                u32 off = p * 16384 + tid * 128 + ((u32)(i ^ (tid & 7))) * 16;
                *(uint4*)(dsm + off) = *(uint4*)&pk[4 * i];
            }
        }
    }
    __syncthreads();

    // ===== Phase 2: A fragments -> registers (warp owns 32 queries) =====
    u32 A[2][2][4][4];
    {
        const int t4 = lane >> 3;
        const int r8 = lane & 7;
#pragma unroll
        for (int p = 0; p < 2; p++)
#pragma unroll
            for (int mt = 0; mt < 2; mt++)
#pragma unroll
                for (int ks = 0; ks < 4; ks++) {
                    u32 row = (u32)(wrp * 32 + mt * 16 + (t4 & 1) * 8 + r8);
                    u32 ch = (u32)(ks * 2 + (t4 >> 1));
                    u32 addr = sbase + p * 16384 + row * 128 + ((ch ^ (row & 7)) * 16);
                    ldsm_x4(addr, A[p][mt][ks][0], A[p][mt][ks][1],
                                  A[p][mt][ks][2], A[p][mt][ks][3]);
                }
    }
    __syncthreads();   // Q planes dead; K planes may overwrite

    // top-9 state per thread (query qbase + tid)
    float tv[9]; int ti[9]; float rmn = -CUDART_INF_F;
#pragma unroll
    for (int j = 0; j < 9; j++) { tv[j] = -CUDART_INF_F; ti[j] = 0; }

    float4* wz = (float4*)(attnw + ((size_t)((b * Hq + h) * Lq + qbase)) * Lq);

    // K staging: thread covers key tid>>2 (32 keys), dims (tid&3)*16 .. +15
    const int krow = tid >> 2;
    const int kd0 = (tid & 3) * 16;
    // 3 products of the 2-plane split: q0k0, q0k1, q1k0
    const int QP[3] = {0, 0, 1};
    const int KP[3] = {0, 1, 0};
    const int ll = lane & 15;

    for (int t = 0; t < NTILES; t++) {
        // ---- load K tile fp32 (32 keys x 64 dims), split to 2 planes ----
        {
            const float4* kp = (const float4*)(K +
                ((size_t)(b * Lq + t * NKT + krow)) * Dq + h * HDq + kd0);
            float e[16];
#pragma unroll
            for (int i = 0; i < 4; i++) {
                float4 v = kp[i];
                e[4 * i] = v.x; e[4 * i + 1] = v.y; e[4 * i + 2] = v.z; e[4 * i + 3] = v.w;
            }
            u32 p0[8], p1[8];
#pragma unroll
            for (int j = 0; j < 8; j++) {
                float a = e[2 * j], c = e[2 * j + 1];
                u32 v0 = cvt2bf(c, a);
                a -= __uint_as_float(v0 << 16);
                c -= __uint_as_float(v0 & 0xFFFF0000u);
                u32 v1 = cvt2bf(c, a);
                p0[j] = v0; p1[j] = v1;
            }
#pragma unroll
            for (int i = 0; i < 2; i++) {
                u32 ch = (u32)((tid & 3) * 2 + i);
                u32 off = (u32)krow * 128 + ((ch ^ ((u32)krow & 7)) * 16);
                *(uint4*)(dsm + off)           = *(uint4*)&p0[4 * i];
                *(uint4*)(dsm + KP1_OFF + off) = *(uint4*)&p1[4 * i];
            }
        }
        // zero-fill this tile's slice of attnw (128 rows x 32 floats)
        if (write_w) {
            const float4 z = make_float4(0.f, 0.f, 0.f, 0.f);
            float4* zp = wz + (size_t)t * 1024;
#pragma unroll
            for (int i = 0; i < 8; i++) zp[i * 128 + tid] = z;
        }
        __syncthreads();   // K planes ready

        // ---- MMA: 4 n-tiles of 8 keys; scores -> smem [128][33] ----
#pragma unroll
        for (int nt = 0; nt < 4; nt++) {
            u32 Bf[2][4][2];
            {
                u32 row = (u32)(nt * 8 + (ll & 7));
                u32 swr = (row & 7);
#pragma unroll
                for (int ks = 0; ks < 4; ks++) {
                    u32 ch = (u32)(ks * 2 + (ll >> 3));
                    u32 off = row * 128 + ((ch ^ swr) * 16);
                    ldsm_x2(sbase + off,           Bf[0][ks][0], Bf[0][ks][1]);
                    ldsm_x2(sbase + KP1_OFF + off, Bf[1][ks][0], Bf[1][ks][1]);
                }
            }
            float cA0 = 0.f, cA1 = 0.f, cA2 = 0.f, cA3 = 0.f;
            float cB0 = 0.f, cB1 = 0.f, cB2 = 0.f, cB3 = 0.f;
#pragma unroll
            for (int pp = 0; pp < 3; pp++) {
                const int qp = QP[pp], kp2 = KP[pp];
#pragma unroll
                for (int ks = 0; ks < 4; ks++) {
                    mma_bf16(cA0, cA1, cA2, cA3,
                             A[qp][0][ks][0], A[qp][0][ks][1],
                             A[qp][0][ks][2], A[qp][0][ks][3],
                             Bf[kp2][ks][0], Bf[kp2][ks][1]);
                    mma_bf16(cB0, cB1, cB2, cB3,
                             A[qp][1][ks][0], A[qp][1][ks][1],
                             A[qp][1][ks][2], A[qp][1][ks][3],
                             Bf[kp2][ks][0], Bf[kp2][ks][1]);
                }
            }
            // scatter C frags to warp-private rows of the score buffer
            {
                const int q0 = wrp * 32 + (lane >> 2);
                const int kk = nt * 8 + (lane & 3) * 2;
                float* sc = (float*)(dsm + SC_OFF);
                sc[(q0 +  0) * 33 + kk]     = cA0;
                sc[(q0 +  0) * 33 + kk + 1] = cA1;
                sc[(q0 +  8) * 33 + kk]     = cA2;
                sc[(q0 +  8) * 33 + kk + 1] = cA3;
                sc[(q0 + 16) * 33 + kk]     = cB0;
                sc[(q0 + 16) * 33 + kk + 1] = cB1;
                sc[(q0 + 24) * 33 + kk]     = cB2;
                sc[(q0 + 24) * 33 + kk + 1] = cB3;
            }
        }
        __syncwarp();      // scores warp-private: scatter visible to own warp

        // ---- stream this thread's 32 scores (ascending keys), top-9 ----
        {
            const float* srow = (const float*)(dsm + SC_OFF) + tid * 33;
#pragma unroll 8
            for (int k = 0; k < NKT; k++) {
                float s = srow[k];
                topN_insert<9>(tv, ti, rmn, s, t * NKT + k);
            }
        }
        __syncthreads();   // scan + all K-plane reads done before next STS
    }

    // ===== init flag state =====
    if (tid == 0) *s_cnt = 0;
    __syncthreads();

    // ===== identify worst (9th); flag near-ties (8th-vs-9th gap) =====
    int w1 = 0;
    {
        float v1 = tv[0]; int i1 = ti[0];
#pragma unroll
        for (int j = 1; j < 9; j++) {
            bool worse = (tv[j] < v1) || (tv[j] == v1 && ti[j] > i1);
            if (worse) { w1 = j; v1 = tv[j]; i1 = ti[j]; }
        }
        float v2 = CUDART_INF_F;
#pragma unroll
        for (int j = 0; j < 9; j++)
            if (j != w1) v2 = fminf(v2, tv[j]);
        if (v2 - v1 < GAP_THRESH) {
            int idx = atomicAdd(s_cnt, 1);
            if (idx < 128) s_list[idx] = tid;
        }
    }

    // ===== softmax over the kept 8; write to sW/sI =====
    __syncthreads();
    {
        float kv[8]; int ki[8]; int c = 0;
#pragma unroll
        for (int j = 0; j < 9; j++)
            if (j != w1) { kv[c] = tv[j]; ki[c] = ti[j]; c++; }
        float mx = kv[0];
#pragma unroll
        for (int j = 1; j < 8; j++) mx = fmaxf(mx, kv[j]);
        float w[8]; float wsum = 0.f;
#pragma unroll
        for (int j = 0; j < 8; j++) { w[j] = expf((kv[j] - mx) * SCALE); wsum += w[j]; }
        float inv = 1.f / wsum;
        float* sW = (float*)(dsm + SW_OFF);
        int*   sI = (int*)(dsm + SI_OFF);
#pragma unroll
        for (int j = 0; j < 8; j++) { sW[tid * 8 + j] = w[j] * inv; sI[tid * 8 + j] = ki[j]; }
    }
    __syncthreads();

    // ===== rescue: recompute flagged rows with exact fp32 f32x2 chain =====
    {
        int ncnt = *s_cnt; if (ncnt > 128) ncnt = 128;
        float* sresc = (float*)(dsm + RS_OFF);
        float* qvec  = (float*)(dsm + RQ_OFF);
        for (int r = 0; r < ncnt; r++) {
            int qq = s_list[r];
            if (tid < 16)
                ((float4*)qvec)[tid] =
                    ((const float4*)(Q + ((size_t)(b * Lq + qbase + qq)) * Dq + h * HDq))[tid];
            __syncthreads();
            u64 q2[32];
            {
                const ulonglong2* qp2 = (const ulonglong2*)qvec;
#pragma unroll
                for (int i = 0; i < 16; i++) {
                    ulonglong2 v = qp2[i];
                    q2[2 * i] = v.x; q2[2 * i + 1] = v.y;
                }
            }
            for (int i = 0; i < 16; i++) {
                int kidx = tid + 128 * i;
                const ulonglong2* kp =
                    (const ulonglong2*)(K + ((size_t)(b * Lq + kidx)) * Dq + h * HDq);
                u64 a0 = 0ull, a1 = 0ull, a2 = 0ull, a3 = 0ull;
#pragma unroll
                for (int ii = 0; ii < 16; ii += 2) {
                    ulonglong2 k0 = kp[ii];
                    ulonglong2 k1 = kp[ii + 1];
                    a0 = ffma2(q2[2 * ii + 0], k0.x, a0);
                    a1 = ffma2(q2[2 * ii + 1], k0.y, a1);
                    a2 = ffma2(q2[2 * ii + 2], k1.x, a2);
                    a3 = ffma2(q2[2 * ii + 3], k1.y, a3);
                }
                u64 a = fadd2(fadd2(a0, a1), fadd2(a2, a3));
                float slo, shi; unpack2(a, slo, shi);
                sresc[kidx] = slo + shi;
            }
            __syncthreads();
            if (tid == 0) {
                float tv8[8]; int ti8[8]; float rm = -CUDART_INF_F;
#pragma unroll
                for (int j = 0; j < 8; j++) { tv8[j] = -CUDART_INF_F; ti8[j] = 0; }
                for (int k = 0; k < Lq; k++)
                    topN_insert<8>(tv8, ti8, rm, sresc[k], k);
                float mx = tv8[0];
#pragma unroll
                for (int j = 1; j < 8; j++) mx = fmaxf(mx, tv8[j]);
                float w8[8]; float wsum = 0.f;
#pragma unroll
                for (int j = 0; j < 8; j++) { w8[j] = expf((tv8[j] - mx) * SCALE); wsum += w8[j]; }
                float inv = 1.f / wsum;
                float* sW = (float*)(dsm + SW_OFF);
                int*   sI = (int*)(dsm + SI_OFF);
#pragma unroll
                for (int j = 0; j < 8; j++) { sW[qq * 8 + j] = w8[j] * inv; sI[qq * 8 + j] = ti8[j]; }
            }
            __syncthreads();
        }
    }

    // ===== scatter attn_weights =====
    if (write_w) {
        const float* sW = (const float*)(dsm + SW_OFF);
        const int*   sI = (const int*)(dsm + SI_OFF);
        float* wrow = attnw + ((size_t)((b * Hq + h) * Lq + qbase + tid)) * Lq;
#pragma unroll
        for (int j = 0; j < 8; j++) wrow[sI[tid * 8 + j]] = sW[tid * 8 + j];
    }

    // ===== coalesced V gather =====
    {
        const float* sW = (const float*)(dsm + SW_OFF);
        const int*   sI = (const int*)(dsm + SI_OFF);
        for (int qq = wrp * 32; qq < wrp * 32 + 32; qq++) {
            float2 acc = make_float2(0.f, 0.f);
#pragma unroll
            for (int j = 0; j < 8; j++) {
                float wv = sW[qq * 8 + j];
                int kidx = sI[qq * 8 + j];
                const float2* vp =
                    (const float2*)(V + ((size_t)(b * Lq + kidx)) * Dq + h * HDq);
                float2 vv = vp[lane];
                acc.x = fmaf(wv, vv.x, acc.x);
                acc.y = fmaf(wv, vv.y, acc.y);
            }
            float2* cp = (float2*)(g_ctx + ((size_t)(b * Lq + qbase + qq)) * Dq + h * HDq);
            cp[lane] = acc;
        }
    }
}

// ---------------------------------------------------------------------------
// Kernel 2: output projection (unchanged): 128x128 tile, BK=8, 8x8 f32x2.
// ---------------------------------------------------------------------------
#define PM 128
#define PN 128
#define PK 8
#define PPAD 132

__global__ __launch_bounds__(256) void proj_kernel(
    const float* __restrict__ Wt,
    const float* __restrict__ bias,
    float* __restrict__ Cout)
{
    __shared__ __align__(16) float As[PK][PPAD];
    __shared__ __align__(16) float Bs[PK][PPAD];

    const int tid = threadIdx.x;
    const int tx = tid & 15;
    const int ty = tid >> 4;
    const int m0 = blockIdx.y * PM;
    const int n0 = blockIdx.x * PN;
    const int lr = tid >> 1;
    const int lk = (tid & 1) * 4;

    u64 acc[8][4];
#pragma unroll
    for (int i = 0; i < 8; i++)
#pragma unroll
        for (int p = 0; p < 4; p++) acc[i][p] = 0ull;

    const float* aptr = g_ctx + (size_t)(m0 + lr) * Dq + lk;
    const float* bptr = Wt + (size_t)(n0 + lr) * Dq + lk;
    float4 av = *(const float4*)aptr;
    float4 bv = *(const float4*)bptr;

    for (int k0 = 0; k0 < Dq; k0 += PK) {
        __syncthreads();
        As[lk + 0][lr] = av.x; As[lk + 1][lr] = av.y;
        As[lk + 2][lr] = av.z; As[lk + 3][lr] = av.w;
        Bs[lk + 0][lr] = bv.x; Bs[lk + 1][lr] = bv.y;
        Bs[lk + 2][lr] = bv.z; Bs[lk + 3][lr] = bv.w;
        if (k0 + PK < Dq) {
            av = *(const float4*)(aptr + k0 + PK);
            bv = *(const float4*)(bptr + k0 + PK);
        }
        __syncthreads();

#pragma unroll
        for (int k = 0; k < PK; k++) {
            float4 a0 = *(const float4*)&As[k][ty * 8];
            float4 a1 = *(const float4*)&As[k][ty * 8 + 4];
            ulonglong2 b0 = *(const ulonglong2*)&Bs[k][tx * 8];
            ulonglong2 b1 = *(const ulonglong2*)&Bs[k][tx * 8 + 4];
            u64 aa;
            aa = pack2(a0.x, a0.x);
            acc[0][0] = ffma2(aa, b0.x, acc[0][0]);
            acc[0][1] = ffma2(aa, b0.y, acc[0][1]);
            acc[0][2] = ffma2(aa, b1.x, acc[0][2]);
            acc[0][3] = ffma2(aa, b1.y, acc[0][3]);
            aa = pack2(a0.y, a0.y);
            acc[1][0] = ffma2(aa, b0.x, acc[1][0]);
            acc[1][1] = ffma2(aa, b0.y, acc[1][1]);
            acc[1][2] = ffma2(aa, b1.x, acc[1][2]);
            acc[1][3] = ffma2(aa, b1.y, acc[1][3]);
            aa = pack2(a0.z, a0.z);
            acc[2][0] = ffma2(aa, b0.x, acc[2][0]);
            acc[2][1] = ffma2(aa, b0.y, acc[2][1]);
            acc[2][2] = ffma2(aa, b1.x, acc[2][2]);
            acc[2][3] = ffma2(aa, b1.y, acc[2][3]);
            aa = pack2(a0.w, a0.w);
            acc[3][0] = ffma2(aa, b0.x, acc[3][0]);
            acc[3][1] = ffma2(aa, b0.y, acc[3][1]);
            acc[3][2] = ffma2(aa, b1.x, acc[3][2]);
            acc[3][3] = ffma2(aa, b1.y, acc[3][3]);
            aa = pack2(a1.x, a1.x);
            acc[4][0] = ffma2(aa, b0.x, acc[4][0]);
            acc[4][1] = ffma2(aa, b0.y, acc[4][1]);
            acc[4][2] = ffma2(aa, b1.x, acc[4][2]);
            acc[4][3] = ffma2(aa, b1.y, acc[4][3]);
            aa = pack2(a1.y, a1.y);
            acc[5][0] = ffma2(aa, b0.x, acc[5][0]);
            acc[5][1] = ffma2(aa, b0.y, acc[5][1]);
            acc[5][2] = ffma2(aa, b1.x, acc[5][2]);
            acc[5][3] = ffma2(aa, b1.y, acc[5][3]);
            aa = pack2(a1.z, a1.z);
            acc[6][0] = ffma2(aa, b0.x, acc[6][0]);
            acc[6][1] = ffma2(aa, b0.y, acc[6][1]);
            acc[6][2] = ffma2(aa, b1.x, acc[6][2]);
            acc[6][3] = ffma2(aa, b1.y, acc[6][3]);
            aa = pack2(a1.w, a1.w);
            acc[7][0] = ffma2(aa, b0.x, acc[7][0]);
            acc[7][1] = ffma2(aa, b0.y, acc[7][1]);
            acc[7][2] = ffma2(aa, b1.x, acc[7][2]);
            acc[7][3] = ffma2(aa, b1.y, acc[7][3]);
        }
    }

    ulonglong2 bb0 = *(const ulonglong2*)&bias[n0 + tx * 8];
    ulonglong2 bb1 = *(const ulonglong2*)&bias[n0 + tx * 8 + 4];
#pragma unroll
    for (int i = 0; i < 8; i++) {
        u64 c0 = fadd2(acc[i][0], bb0.x);
        u64 c1 = fadd2(acc[i][1], bb0.y);
        u64 c2 = fadd2(acc[i][2], bb1.x);
        u64 c3 = fadd2(acc[i][3], bb1.y);
        float* crow = Cout + (size_t)(m0 + ty * 8 + i) * Dq + n0 + tx * 8;
        ((ulonglong2*)crow)[0] = make_ulonglong2(c0, c1);
        ((ulonglong2*)crow)[1] = make_ulonglong2(c2, c3);
    }
}

// ---------------------------------------------------------------------------
extern "C" void kernel_launch(void* const* d_in, const int* in_sizes, int n_in,
                              void* d_out, int out_size)
{
    const float* Q    = (const float*)d_in[0];
    const float* K    = (const float*)d_in[1];
    const float* V    = (const float*)d_in[2];
    const float* W    = (const float*)d_in[3];
    const float* bias = (const float*)d_in[4];
    float* out = (float*)d_out;

    const size_t N_ATT = (size_t)Bq * Lq * Dq;
    const size_t N_W   = (size_t)Bq * Hq * Lq * Lq;
    const int has_w = ((size_t)out_size >= N_ATT + N_W) ? 1 : 0;
    float* attnw = out + N_ATT;

    dim3 g1(Lq / 128, Hq, Bq);
    attn_topk_kernel<<<g1, 128, DSM_SZ>>>(Q, K, V, attnw, has_w);

    dim3 g2(Dq / PN, (Bq * Lq) / PM);
    proj_kernel<<<g2, 256>>>(W, bias, out);
}